// round 1
// baseline (speedup 1.0000x reference)
#include <cuda_runtime.h>

#define HDIM 50
#define TLEN 512
#define NBATCH 4096
#define BPT 4                  // batches per thread
#define NSLOT 8                // batch slots per CTA
#define NB (BPT*NSLOT)         // 32 batches per CTA
#define NTH (NSLOT*HDIM)       // 400 threads per CTA
#define NCTA (NBATCH/NB)       // 128 CTAs
#define HP 36                  // h buffer pitch (floats) -> breaks bank conflicts

typedef unsigned long long u64;

__device__ __forceinline__ u64 pk2(float lo, float hi) {
    u64 r; asm("mov.b64 %0, {%1,%2};" : "=l"(r) : "f"(lo), "f"(hi)); return r;
}
__device__ __forceinline__ void upk2(u64 v, float& lo, float& hi) {
    asm("mov.b64 {%0,%1}, %2;" : "=f"(lo), "=f"(hi) : "l"(v));
}
// packed fp32x2 FMA (Blackwell 2x fp32 path; only reachable via PTX)
__device__ __forceinline__ u64 ffma2(u64 a, u64 b, u64 c) {
    u64 d; asm("fma.rn.f32x2 %0, %1, %2, %3;" : "=l"(d) : "l"(a), "l"(b), "l"(c)); return d;
}

__device__ __forceinline__ float sigf(float z) {
    return __fdividef(1.0f, 1.0f + __expf(-z));
}
__device__ __forceinline__ float tanhfast(float z) {
    // tanh(z) = 2*sigmoid(2z) - 1
    return fmaf(2.0f, sigf(2.0f * z), -1.0f);
}

// accumulate 4-gate matvec for unit u over K=50 source-h values, 4 batches
__device__ __forceinline__ void matvec_acc(const float* __restrict__ W,
                                           const float* __restrict__ hbase,
                                           int u, int bslot,
                                           u64 aif[BPT], u64 ago[BPT]) {
    const ulonglong2* __restrict__ Wp = (const ulonglong2*)W;  // [k*HDIM + u] -> ((wi,wf),(wg,wo))
#pragma unroll 5
    for (int k = 0; k < HDIM; k++) {
        ulonglong2 w = Wp[k * HDIM + u];
        float4 h4 = *(const float4*)(hbase + k * HP + 4 * bslot);
        float hv0 = h4.x, hv1 = h4.y, hv2 = h4.z, hv3 = h4.w;
        u64 hp;
        hp = pk2(hv0, hv0); aif[0] = ffma2(w.x, hp, aif[0]); ago[0] = ffma2(w.y, hp, ago[0]);
        hp = pk2(hv1, hv1); aif[1] = ffma2(w.x, hp, aif[1]); ago[1] = ffma2(w.y, hp, ago[1]);
        hp = pk2(hv2, hv2); aif[2] = ffma2(w.x, hp, aif[2]); ago[2] = ffma2(w.y, hp, ago[2]);
        hp = pk2(hv3, hv3); aif[3] = ffma2(w.x, hp, aif[3]); ago[3] = ffma2(w.y, hp, ago[3]);
    }
}

__device__ __forceinline__ void cellupd(u64 aif, u64 ago, float& c, float& h) {
    float zi, zf, zg, zo;
    upk2(aif, zi, zf);
    upk2(ago, zg, zo);
    float ig = sigf(zi);
    float fg = sigf(zf);
    float gg = tanhfast(zg);
    float og = sigf(zo);
    c = fmaf(fg, c, ig * gg);
    h = og * tanhfast(c);
}

// dynamic smem layout (floats):
//  W0  [HDIM k][HDIM u][4 gates]      10000
//  W1i [HDIM k][HDIM u][4 gates]      10000
//  W1h [HDIM k][HDIM u][4 gates]      10000
//  h0b [2][HDIM][HP]                   3600
//  h1b [2][HDIM][HP]                   3600
//  xs  [2][NB]                           64
#define SMEM_FLOATS (30000 + 2*HDIM*HP*2 + 2*NB)

__global__ void __launch_bounds__(NTH, 1)
lstm_kernel(const float* __restrict__ x,
            const float* __restrict__ w_ih0, const float* __restrict__ w_hh0,
            const float* __restrict__ b_ih0, const float* __restrict__ b_hh0,
            const float* __restrict__ w_ih1, const float* __restrict__ w_hh1,
            const float* __restrict__ b_ih1, const float* __restrict__ b_hh1,
            const float* __restrict__ fc_w,  const float* __restrict__ fc_b,
            float* __restrict__ out) {
    extern __shared__ float smem[];
    float* W0  = smem;
    float* W1i = W0  + 4 * HDIM * HDIM;
    float* W1h = W1i + 4 * HDIM * HDIM;
    float* h0b = W1h + 4 * HDIM * HDIM;
    float* h1b = h0b + 2 * HDIM * HP;
    float* xs  = h1b + 2 * HDIM * HP;

    const int tid   = threadIdx.x;
    const int u     = tid % HDIM;
    const int bslot = tid / HDIM;
    const int b0    = blockIdx.x * NB;

    // ---- stage weights into smem, re-laid-out [k][u][gate] ----
    for (int i = tid; i < 4 * HDIM * HDIM; i += NTH) {
        int r = i / HDIM;        // row in [4H, H] weight: r = g*H + uu
        int k = i % HDIM;
        int g = r / HDIM;
        int uu = r % HDIM;
        int o = (k * HDIM + uu) * 4 + g;
        W0[o]  = w_hh0[i];
        W1i[o] = w_ih1[i];
        W1h[o] = w_hh1[i];
    }
    // zero initial h buffers (buffer 0)
    for (int i = tid; i < HDIM * HP; i += NTH) {
        h0b[i] = 0.0f;
        h1b[i] = 0.0f;
    }
    // stage x for t=0
    if (tid < NB) xs[tid] = x[(size_t)(b0 + tid) * TLEN + 0];

    // ---- per-thread constants ----
    // layer0 input weights (input dim 1) and combined biases, packed by gate pairs
    u64 w0if = pk2(w_ih0[0 * HDIM + u], w_ih0[1 * HDIM + u]);
    u64 w0go = pk2(w_ih0[2 * HDIM + u], w_ih0[3 * HDIM + u]);
    u64 bias0if = pk2(b_ih0[0 * HDIM + u] + b_hh0[0 * HDIM + u],
                      b_ih0[1 * HDIM + u] + b_hh0[1 * HDIM + u]);
    u64 bias0go = pk2(b_ih0[2 * HDIM + u] + b_hh0[2 * HDIM + u],
                      b_ih0[3 * HDIM + u] + b_hh0[3 * HDIM + u]);
    u64 bias1if = pk2(b_ih1[0 * HDIM + u] + b_hh1[0 * HDIM + u],
                      b_ih1[1 * HDIM + u] + b_hh1[1 * HDIM + u]);
    u64 bias1go = pk2(b_ih1[2 * HDIM + u] + b_hh1[2 * HDIM + u],
                      b_ih1[3 * HDIM + u] + b_hh1[3 * HDIM + u]);

    float c0[BPT], c1[BPT], hn0[BPT], hn1[BPT];
#pragma unroll
    for (int b = 0; b < BPT; b++) { c0[b] = 0.0f; c1[b] = 0.0f; hn1[b] = 0.0f; }

    __syncthreads();

    int cur = 0;
    for (int t = 0; t < TLEN; t++) {
        const int nxt = cur ^ 1;

        // ===== Phase A: layer 0 =====
        u64 aif[BPT], ago[BPT];
#pragma unroll
        for (int b = 0; b < BPT; b++) {
            float xv = xs[cur * NB + 4 * bslot + b];
            u64 xp = pk2(xv, xv);
            aif[b] = ffma2(w0if, xp, bias0if);
            ago[b] = ffma2(w0go, xp, bias0go);
        }
        matvec_acc(W0, h0b + cur * HDIM * HP, u, bslot, aif, ago);
#pragma unroll
        for (int b = 0; b < BPT; b++) cellupd(aif[b], ago[b], c0[b], hn0[b]);
        *(float4*)(h0b + nxt * HDIM * HP + u * HP + 4 * bslot) =
            make_float4(hn0[0], hn0[1], hn0[2], hn0[3]);
        __syncthreads();

        // ===== Phase B: layer 1 =====
#pragma unroll
        for (int b = 0; b < BPT; b++) { aif[b] = bias1if; ago[b] = bias1go; }
        matvec_acc(W1i, h0b + nxt * HDIM * HP, u, bslot, aif, ago);  // input = new h0
        matvec_acc(W1h, h1b + cur * HDIM * HP, u, bslot, aif, ago);  // recurrent h1
#pragma unroll
        for (int b = 0; b < BPT; b++) cellupd(aif[b], ago[b], c1[b], hn1[b]);
        *(float4*)(h1b + nxt * HDIM * HP + u * HP + 4 * bslot) =
            make_float4(hn1[0], hn1[1], hn1[2], hn1[3]);

        // stage x for next step
        if (tid < NB && (t + 1) < TLEN)
            xs[nxt * NB + tid] = x[(size_t)(b0 + tid) * TLEN + (t + 1)];

        __syncthreads();
        cur = nxt;
    }

    // ===== FC epilogue: out[b] = fc_w . h1_last[b] + fc_b =====
    // reuse h0b buffer 0 as reduction scratch: red[u][batch]
    float fw = fc_w[u];
    *(float4*)(h0b + u * HP + 4 * bslot) =
        make_float4(fw * hn1[0], fw * hn1[1], fw * hn1[2], fw * hn1[3]);
    __syncthreads();
    if (tid < NB) {
        float s = fc_b[0];
#pragma unroll 10
        for (int k = 0; k < HDIM; k++) s += h0b[k * HP + tid];
        out[b0 + tid] = s;
    }
}

extern "C" void kernel_launch(void* const* d_in, const int* in_sizes, int n_in,
                              void* d_out, int out_size) {
    const float* x     = (const float*)d_in[0];
    const float* w_ih0 = (const float*)d_in[1];
    const float* w_hh0 = (const float*)d_in[2];
    const float* b_ih0 = (const float*)d_in[3];
    const float* b_hh0 = (const float*)d_in[4];
    const float* w_ih1 = (const float*)d_in[5];
    const float* w_hh1 = (const float*)d_in[6];
    const float* b_ih1 = (const float*)d_in[7];
    const float* b_hh1 = (const float*)d_in[8];
    const float* fc_w  = (const float*)d_in[9];
    const float* fc_b  = (const float*)d_in[10];
    float* out = (float*)d_out;

    const size_t smem_bytes = SMEM_FLOATS * sizeof(float);
    cudaFuncSetAttribute(lstm_kernel, cudaFuncAttributeMaxDynamicSharedMemorySize,
                         (int)smem_bytes);
    lstm_kernel<<<NCTA, NTH, smem_bytes>>>(x, w_ih0, w_hh0, b_ih0, b_hh0,
                                           w_ih1, w_hh1, b_ih1, b_hh1,
                                           fc_w, fc_b, out);
}